// round 14
// baseline (speedup 1.0000x reference)
#include <cuda_runtime.h>
#include <cuda_bf16.h>
#include <cuda_fp16.h>
#include <math.h>
#include <stdint.h>

// Problem constants
#define T_STEPS 16
#define BATCH   128
#define IN_DIM  12288
#define H1_DIM  256
#define H2_DIM  512

// ---------------------------------------------------------------------------
// Device-global scratch (no allocation allowed)
// ---------------------------------------------------------------------------
__device__ __align__(256) __half g_Xh  [2048 * 12288];
__device__ __align__(256) __half g_W1h [1024 * 12288];

__device__ __align__(256) __nv_bfloat16 g_W2hi[2048 * 256];
__device__ __align__(256) __nv_bfloat16 g_W2lo[2048 * 256];
__device__ __align__(256) __nv_bfloat16 g_Whh1hi[1024 * 256];
__device__ __align__(256) __nv_bfloat16 g_Whh1lo[1024 * 256];
__device__ __align__(256) __nv_bfloat16 g_Whh2hi[2048 * 512];
__device__ __align__(256) __nv_bfloat16 g_Whh2lo[2048 * 512];

// h sequences incl. leading zero slice: slice s = h after step s-1 (s=0 -> zeros)
__device__ __align__(256) __nv_bfloat16 g_y1hi[17 * 128 * 256];
__device__ __align__(256) __nv_bfloat16 g_y1lo[17 * 128 * 256];
__device__ __align__(256) __nv_bfloat16 g_h2hi[17 * 128 * 512];
__device__ __align__(256) __nv_bfloat16 g_h2lo[17 * 128 * 512];

__device__ float g_pre1 [2 * 2048 * 1024];  // GEMM1 K-split partials (z=2)
__device__ float g_pre2 [2048 * 2048];      // [T*B, 4*H2]
__device__ float g_part1[8 * 128 * 1024];   // rec k-split partials layer 1
__device__ float g_part2[8 * 128 * 2048];   // rec k-split partials layer 2
__device__ float g_c1[128 * 256];
__device__ float g_c2[128 * 512];

// fast sigmoid/tanh via approx MUFU ops (rel err ~1e-6, safe at saturation)
__device__ __forceinline__ float sigmoidf_(float x) {
    float t, r;
    asm("ex2.approx.f32 %0, %1;" : "=f"(t) : "f"(-1.4426950408889634f * x));
    asm("rcp.approx.f32 %0, %1;" : "=f"(r) : "f"(1.0f + t));
    return r;
}
__device__ __forceinline__ float tanhf_(float x) {
    return 2.0f * sigmoidf_(2.0f * x) - 1.0f;
}

// ---------------------------------------------------------------------------
// PTX helpers (compute_103-safe: cp.async + ldmatrix + mma.sync only)
// ---------------------------------------------------------------------------
__device__ __forceinline__ uint32_t smem_u32(const void* p) {
    uint32_t a;
    asm("{ .reg .u64 t; cvta.to.shared.u64 t, %1; cvt.u32.u64 %0, t; }"
        : "=r"(a) : "l"(p));
    return a;
}

template <int N>
__device__ __forceinline__ void cpwait() {
    asm volatile("cp.async.wait_group %0;" :: "n"(N));
}

__device__ __forceinline__ void cp16(uint32_t dst, const void* src) {
    asm volatile("cp.async.cg.shared.global [%0], [%1], 16;"
                 :: "r"(dst), "l"(src));
}

__device__ __forceinline__ void cpcommit() {
    asm volatile("cp.async.commit_group;");
}

__device__ __forceinline__ void ldsm4(uint32_t* r, uint32_t addr) {
    asm volatile("ldmatrix.sync.aligned.m8n8.x4.shared.b16 {%0,%1,%2,%3}, [%4];"
                 : "=r"(r[0]), "=r"(r[1]), "=r"(r[2]), "=r"(r[3]) : "r"(addr));
}

__device__ __forceinline__ void mma_bf16(float* d, const uint32_t* a,
                                         uint32_t b0, uint32_t b1) {
    asm("mma.sync.aligned.m16n8k16.row.col.f32.bf16.bf16.f32 "
        "{%0,%1,%2,%3}, {%4,%5,%6,%7}, {%8,%9}, {%0,%1,%2,%3};"
        : "+f"(d[0]), "+f"(d[1]), "+f"(d[2]), "+f"(d[3])
        : "r"(a[0]), "r"(a[1]), "r"(a[2]), "r"(a[3]), "r"(b0), "r"(b1));
}

__device__ __forceinline__ void mma_f16(float* d, const uint32_t* a,
                                        uint32_t b0, uint32_t b1) {
    asm("mma.sync.aligned.m16n8k16.row.col.f32.f16.f16.f32 "
        "{%0,%1,%2,%3}, {%4,%5,%6,%7}, {%8,%9}, {%0,%1,%2,%3};"
        : "+f"(d[0]), "+f"(d[1]), "+f"(d[2]), "+f"(d[3])
        : "r"(a[0]), "r"(a[1]), "r"(a[2]), "r"(a[3]), "r"(b0), "r"(b1));
}

// ---------------------------------------------------------------------------
// Zero the recurrent states (h slice 0 + c)
// ---------------------------------------------------------------------------
__global__ void zero_states_kernel() {
    int i = blockIdx.x * blockDim.x + threadIdx.x;
    if (i < 128 * 256) {
        g_y1hi[i] = __nv_bfloat16(0.0f);
        g_y1lo[i] = __nv_bfloat16(0.0f);
        g_c1[i] = 0.0f;
    }
    if (i < 128 * 512) {
        g_h2hi[i] = __nv_bfloat16(0.0f);
        g_h2lo[i] = __nv_bfloat16(0.0f);
        g_c2[i] = 0.0f;
    }
}

// ---------------------------------------------------------------------------
// fp32 -> (hi, lo) bf16 split
// ---------------------------------------------------------------------------
__global__ void split_kernel(const float* __restrict__ x,
                             __nv_bfloat16* __restrict__ hi,
                             __nv_bfloat16* __restrict__ lo, int n4) {
    int i = blockIdx.x * blockDim.x + threadIdx.x;
    if (i >= n4) return;
    float4 v = ((const float4*)x)[i];
    __nv_bfloat16 h0 = __float2bfloat16(v.x);
    __nv_bfloat16 h1 = __float2bfloat16(v.y);
    __nv_bfloat16 h2 = __float2bfloat16(v.z);
    __nv_bfloat16 h3 = __float2bfloat16(v.w);
    __nv_bfloat16 l0 = __float2bfloat16(v.x - __bfloat162float(h0));
    __nv_bfloat16 l1 = __float2bfloat16(v.y - __bfloat162float(h1));
    __nv_bfloat16 l2 = __float2bfloat16(v.z - __bfloat162float(h2));
    __nv_bfloat16 l3 = __float2bfloat16(v.w - __bfloat162float(h3));
    ((__nv_bfloat162*)hi)[i * 2 + 0] = __nv_bfloat162(h0, h1);
    ((__nv_bfloat162*)hi)[i * 2 + 1] = __nv_bfloat162(h2, h3);
    ((__nv_bfloat162*)lo)[i * 2 + 0] = __nv_bfloat162(l0, l1);
    ((__nv_bfloat162*)lo)[i * 2 + 1] = __nv_bfloat162(l2, l3);
}

// fp32 -> fp16 quantize
__global__ void quant_f16_kernel(const float* __restrict__ x,
                                 __half* __restrict__ hi, int n4) {
    int i = blockIdx.x * blockDim.x + threadIdx.x;
    if (i >= n4) return;
    float4 v = ((const float4*)x)[i];
    ((__half2*)hi)[i * 2 + 0] = __halves2half2(__float2half(v.x), __float2half(v.y));
    ((__half2*)hi)[i * 2 + 1] = __halves2half2(__float2half(v.z), __float2half(v.w));
}

// ---------------------------------------------------------------------------
// Shared GEMM geometry
// ---------------------------------------------------------------------------
#define GSTAGES 3
#define TILE_B 8192                       // one 128x32 x 16-bit tile
#define GSTAGE_BYTES (4 * TILE_B)         // bf16 3-term: 4 tiles/stage
#define GSMEM_TOTAL (GSTAGES * GSTAGE_BYTES)
#define OSTAGE_BYTES (2 * TILE_B)         // f16 1-term: 2 tiles/stage
#define OSMEM_TOTAL (GSTAGES * OSTAGE_BYTES)

// swizzled offset of (row, chunk) within a tile; chunk = 16B = 8 elems
__device__ __forceinline__ uint32_t swz(int row, int c) {
    return (uint32_t)(row * 64 + 16 * (c ^ ((row >> 1) & 3)));
}

// ---------------------------------------------------------------------------
// Split-bf16 HMMA GEMM (3 terms) with optional K-split partials.
// grid = (N/128, M/128, KZ); Ksub = K/KZ (mult of 32); ldK = row stride.
// ---------------------------------------------------------------------------
__global__ __launch_bounds__(256) void gemm_bf16split(
    const __nv_bfloat16* __restrict__ Ahi, const __nv_bfloat16* __restrict__ Alo,
    const __nv_bfloat16* __restrict__ Bhi, const __nv_bfloat16* __restrict__ Blo,
    float* __restrict__ C, int N, int ldK, int Ksub, long partStride)
{
    extern __shared__ __align__(1024) char gsm[];
    const uint32_t sbase = smem_u32(gsm);
    const int tid = threadIdx.x;
    const int wid = tid >> 5;
    const int lane = tid & 31;
    const int m0 = blockIdx.y * 128;
    const int n0 = blockIdx.x * 128;
    const int koff = blockIdx.z * Ksub;
    const int NK = Ksub >> 5;

    C += (long)blockIdx.z * partStride;

    const int wm = (wid & 1) * 64;
    const int wn = (wid >> 1) * 32;

    auto load_chunk = [&](int ko, int s) {
        const uint32_t stg = sbase + s * GSTAGE_BYTES;
        const int k0 = koff + ko * 32;
#pragma unroll
        for (int it = 0; it < 8; it++) {
            int flat = tid + it * 256;
            int tile = flat >> 9;
            int within = flat & 511;
            int row = within >> 2;
            int c = within & 3;
            const __nv_bfloat16* gp;
            if (tile == 0)      gp = Ahi + (long)(m0 + row) * ldK + k0 + c * 8;
            else if (tile == 1) gp = Alo + (long)(m0 + row) * ldK + k0 + c * 8;
            else if (tile == 2) gp = Bhi + (long)(n0 + row) * ldK + k0 + c * 8;
            else                gp = Blo + (long)(n0 + row) * ldK + k0 + c * 8;
            cp16(stg + tile * TILE_B + swz(row, c), gp);
        }
        cpcommit();
    };

    const int npre = (NK < GSTAGES) ? NK : GSTAGES;
    for (int k = 0; k < npre; k++) load_chunk(k, k);

    float acc[4][4][4];
#pragma unroll
    for (int i = 0; i < 4; i++)
#pragma unroll
        for (int j = 0; j < 4; j++)
#pragma unroll
            for (int q = 0; q < 4; q++) acc[i][j][q] = 0.0f;

    const int a_row_off = ((lane >> 3) & 1) * 8 + (lane & 7);
    const int a_k_off = (lane >> 4);
    const int b_row = wn + lane;

    for (int k = 0; k < NK; k++) {
        const int s = k % GSTAGES;
        const int rem = NK - 1 - k;
        if (rem >= GSTAGES - 1)      cpwait<GSTAGES - 1>();
        else if (rem == 1)           cpwait<1>();
        else                         cpwait<0>();
        __syncthreads();

        const uint32_t stg = sbase + s * GSTAGE_BYTES;
        const uint32_t ah = stg;
        const uint32_t al = stg + TILE_B;
        const uint32_t bh = stg + 2 * TILE_B;
        const uint32_t bl = stg + 3 * TILE_B;

#pragma unroll
        for (int ks = 0; ks < 2; ks++) {
            const int kc = ks * 2;
            uint32_t Ah[4][4], Al[4][4];
            uint32_t Bh0[4], Bh1[4], Bl0[4], Bl1[4];
#pragma unroll
            for (int mt = 0; mt < 4; mt++) {
                const int r = wm + mt * 16 + a_row_off;
                ldsm4(Ah[mt], ah + swz(r, kc + a_k_off));
                ldsm4(Al[mt], al + swz(r, kc + a_k_off));
            }
            ldsm4(Bh0, bh + swz(b_row, kc));
            ldsm4(Bh1, bh + swz(b_row, kc + 1));
            ldsm4(Bl0, bl + swz(b_row, kc));
            ldsm4(Bl1, bl + swz(b_row, kc + 1));
#pragma unroll
            for (int mt = 0; mt < 4; mt++)
#pragma unroll
                for (int nt = 0; nt < 4; nt++)
                    mma_bf16(acc[mt][nt], Ah[mt], Bh0[nt], Bh1[nt]);
#pragma unroll
            for (int mt = 0; mt < 4; mt++)
#pragma unroll
                for (int nt = 0; nt < 4; nt++)
                    mma_bf16(acc[mt][nt], Ah[mt], Bl0[nt], Bl1[nt]);
#pragma unroll
            for (int mt = 0; mt < 4; mt++)
#pragma unroll
                for (int nt = 0; nt < 4; nt++)
                    mma_bf16(acc[mt][nt], Al[mt], Bh0[nt], Bh1[nt]);
        }
        __syncthreads();
        if (k + GSTAGES < NK) load_chunk(k + GSTAGES, s);
    }

#pragma unroll
    for (int mt = 0; mt < 4; mt++) {
#pragma unroll
        for (int nt = 0; nt < 4; nt++) {
            const int row = m0 + wm + mt * 16 + (lane >> 2);
            const int col = n0 + wn + nt * 8 + (lane & 3) * 2;
            float2 v0 = make_float2(acc[mt][nt][0], acc[mt][nt][1]);
            float2 v1 = make_float2(acc[mt][nt][2], acc[mt][nt][3]);
            *(float2*)&C[(long)row * N + col] = v0;
            *(float2*)&C[(long)(row + 8) * N + col] = v1;
        }
    }
}

// ---------------------------------------------------------------------------
// fp16 1-term GEMM (GEMM1): C = A_f16 * B_f16^T, fp32 accum.
// 2 smem tiles per stage. grid = (N/128, M/128, KZ).
// ---------------------------------------------------------------------------
__global__ __launch_bounds__(256) void gemm_f16_1term(
    const __half* __restrict__ A, const __half* __restrict__ B,
    float* __restrict__ C, int N, int ldK, int Ksub, long partStride)
{
    extern __shared__ __align__(1024) char gsm[];
    const uint32_t sbase = smem_u32(gsm);
    const int tid = threadIdx.x;
    const int wid = tid >> 5;
    const int lane = tid & 31;
    const int m0 = blockIdx.y * 128;
    const int n0 = blockIdx.x * 128;
    const int koff = blockIdx.z * Ksub;
    const int NK = Ksub >> 5;

    C += (long)blockIdx.z * partStride;

    const int wm = (wid & 1) * 64;
    const int wn = (wid >> 1) * 32;

    auto load_chunk = [&](int ko, int s) {
        const uint32_t stg = sbase + s * OSTAGE_BYTES;
        const int k0 = koff + ko * 32;
#pragma unroll
        for (int it = 0; it < 4; it++) {
            int flat = tid + it * 256;        // 0..1023
            int tile = flat >> 9;             // 0..1
            int within = flat & 511;
            int row = within >> 2;
            int c = within & 3;
            const __half* gp = (tile == 0)
                ? A + (long)(m0 + row) * ldK + k0 + c * 8
                : B + (long)(n0 + row) * ldK + k0 + c * 8;
            cp16(stg + tile * TILE_B + swz(row, c), gp);
        }
        cpcommit();
    };

    const int npre = (NK < GSTAGES) ? NK : GSTAGES;
    for (int k = 0; k < npre; k++) load_chunk(k, k);

    float acc[4][4][4];
#pragma unroll
    for (int i = 0; i < 4; i++)
#pragma unroll
        for (int j = 0; j < 4; j++)
#pragma unroll
            for (int q = 0; q < 4; q++) acc[i][j][q] = 0.0f;

    const int a_row_off = ((lane >> 3) & 1) * 8 + (lane & 7);
    const int a_k_off = (lane >> 4);
    const int b_row = wn + lane;

    for (int k = 0; k < NK; k++) {
        const int s = k % GSTAGES;
        const int rem = NK - 1 - k;
        if (rem >= GSTAGES - 1)      cpwait<GSTAGES - 1>();
        else if (rem == 1)           cpwait<1>();
        else                         cpwait<0>();
        __syncthreads();

        const uint32_t stg = sbase + s * OSTAGE_BYTES;
        const uint32_t ah = stg;
        const uint32_t bh = stg + TILE_B;

#pragma unroll
        for (int ks = 0; ks < 2; ks++) {
            const int kc = ks * 2;
            uint32_t Ah[4][4];
            uint32_t Bh0[4], Bh1[4];
#pragma unroll
            for (int mt = 0; mt < 4; mt++) {
                const int r = wm + mt * 16 + a_row_off;
                ldsm4(Ah[mt], ah + swz(r, kc + a_k_off));
            }
            ldsm4(Bh0, bh + swz(b_row, kc));
            ldsm4(Bh1, bh + swz(b_row, kc + 1));
#pragma unroll
            for (int mt = 0; mt < 4; mt++)
#pragma unroll
                for (int nt = 0; nt < 4; nt++)
                    mma_f16(acc[mt][nt], Ah[mt], Bh0[nt], Bh1[nt]);
        }
        __syncthreads();
        if (k + GSTAGES < NK) load_chunk(k + GSTAGES, s);
    }

#pragma unroll
    for (int mt = 0; mt < 4; mt++) {
#pragma unroll
        for (int nt = 0; nt < 4; nt++) {
            const int row = m0 + wm + mt * 16 + (lane >> 2);
            const int col = n0 + wn + nt * 8 + (lane & 3) * 2;
            float2 v0 = make_float2(acc[mt][nt][0], acc[mt][nt][1]);
            float2 v1 = make_float2(acc[mt][nt][2], acc[mt][nt][3]);
            *(float2*)&C[(long)row * N + col] = v0;
            *(float2*)&C[(long)(row + 8) * N + col] = v1;
        }
    }
}

// ---------------------------------------------------------------------------
// Gate kernel: sum KZ rec partials + PREZ pre slices + bias, nonlinearity,
// c/h update; h emitted as bf16 hi/lo (next-step GEMM input), optional fp32 y.
// ---------------------------------------------------------------------------
template <int H, int KZ, int PREZ, bool L2OUT>
__global__ __launch_bounds__(256) void lstm_gates2(
    const float* __restrict__ part,     // [KZ][128][4H]
    const float* __restrict__ pre,      // offset to t; slices stride = pstride
    long pstride,
    const float* __restrict__ bias,     // [4H]
    float* __restrict__ c,              // [128][H]
    __nv_bfloat16* __restrict__ hhi,    // next h slice (hi)
    __nv_bfloat16* __restrict__ hlo,    // next h slice (lo)
    float* __restrict__ out)            // fp32 y slice (layer 2) or unused
{
    const int idx = blockIdx.x * 256 + threadIdx.x;   // b*H + j
    const int b = idx / H;
    const int j = idx % H;

    float gate[4];
#pragma unroll
    for (int g = 0; g < 4; g++) {
        const int o = b * 4 * H + g * H + j;
        float v = bias[g * H + j];
#pragma unroll
        for (int z = 0; z < PREZ; z++) v += pre[(long)z * pstride + o];
#pragma unroll
        for (int z = 0; z < KZ; z++) v += part[(long)z * (128 * 4 * H) + o];
        gate[g] = v;
    }

    const float cold = c[idx];
    const float cn = sigmoidf_(gate[1]) * cold + sigmoidf_(gate[0]) * tanhf_(gate[2]);
    const float hn = sigmoidf_(gate[3]) * tanhf_(cn);

    c[idx] = cn;
    __nv_bfloat16 hv = __float2bfloat16(hn);
    hhi[idx] = hv;
    hlo[idx] = __float2bfloat16(hn - __bfloat162float(hv));
    if (L2OUT) out[idx] = hn;
}

// ---------------------------------------------------------------------------
extern "C" void kernel_launch(void* const* d_in, const int* in_sizes, int n_in,
                              void* d_out, int out_size)
{
    const float* inp  = (const float*)d_in[0];   // [128,16,12288] flat [2048,12288]
    const float* Wih1 = (const float*)d_in[1];   // [1024,12288]
    const float* Whh1 = (const float*)d_in[2];   // [1024,256]
    const float* b1   = (const float*)d_in[3];   // [1024]
    const float* Wih2 = (const float*)d_in[4];   // [2048,256]
    const float* Whh2 = (const float*)d_in[5];   // [2048,512]
    const float* b2   = (const float*)d_in[6];   // [2048]
    float* out = (float*)d_out;                  // [16,128,512] flat

    __half *Xh, *W1h;
    __nv_bfloat16 *W2hi, *W2lo;
    __nv_bfloat16 *R1hi, *R1lo, *R2hi, *R2lo, *y1hi, *y1lo, *h2hi, *h2lo;
    float *pre1, *pre2, *part1, *part2, *c1, *c2;
    cudaGetSymbolAddress((void**)&Xh,   g_Xh);
    cudaGetSymbolAddress((void**)&W1h,  g_W1h);
    cudaGetSymbolAddress((void**)&W2hi, g_W2hi);
    cudaGetSymbolAddress((void**)&W2lo, g_W2lo);
    cudaGetSymbolAddress((void**)&R1hi, g_Whh1hi);
    cudaGetSymbolAddress((void**)&R1lo, g_Whh1lo);
    cudaGetSymbolAddress((void**)&R2hi, g_Whh2hi);
    cudaGetSymbolAddress((void**)&R2lo, g_Whh2lo);
    cudaGetSymbolAddress((void**)&y1hi, g_y1hi);
    cudaGetSymbolAddress((void**)&y1lo, g_y1lo);
    cudaGetSymbolAddress((void**)&h2hi, g_h2hi);
    cudaGetSymbolAddress((void**)&h2lo, g_h2lo);
    cudaGetSymbolAddress((void**)&pre1, g_pre1);
    cudaGetSymbolAddress((void**)&pre2, g_pre2);
    cudaGetSymbolAddress((void**)&part1, g_part1);
    cudaGetSymbolAddress((void**)&part2, g_part2);
    cudaGetSymbolAddress((void**)&c1, g_c1);
    cudaGetSymbolAddress((void**)&c2, g_c2);

    cudaFuncSetAttribute(gemm_bf16split,
                         cudaFuncAttributeMaxDynamicSharedMemorySize, GSMEM_TOTAL);
    cudaFuncSetAttribute(gemm_f16_1term,
                         cudaFuncAttributeMaxDynamicSharedMemorySize, OSMEM_TOTAL);

    // 0) fresh recurrent state (h slice 0 = 0, c = 0)
    zero_states_kernel<<<256, 256>>>();

    // 1) precision conversions
    quant_f16_kernel<<<(2048 * 12288 / 4 + 255) / 256, 256>>>(inp, Xh, 2048 * 12288 / 4);
    quant_f16_kernel<<<(1024 * 12288 / 4 + 255) / 256, 256>>>(Wih1, W1h, 1024 * 12288 / 4);
    split_kernel<<<(2048 * 256 / 4 + 255) / 256, 256>>>(Wih2, W2hi, W2lo, 2048 * 256 / 4);
    split_kernel<<<(1024 * 256 / 4 + 255) / 256, 256>>>(Whh1, R1hi, R1lo, 1024 * 256 / 4);
    split_kernel<<<(2048 * 512 / 4 + 255) / 256, 256>>>(Whh2, R2hi, R2lo, 2048 * 512 / 4);

    // 2) layer-1 input projection (fp16 1-term HMMA, K-split x2): pre1[2][2048,1024]
    gemm_f16_1term<<<dim3(8, 16, 2), 256, OSMEM_TOTAL>>>(
        Xh, W1h, pre1, 1024, IN_DIM, IN_DIM / 2, (long)2048 * 1024);

    // 3) layer-1 recurrence: per step, HMMA k-split partial GEMM + gates
    for (int t = 0; t < T_STEPS; t++) {
        gemm_bf16split<<<dim3(8, 1, 8), 256, GSMEM_TOTAL>>>(
            y1hi + (long)t * 128 * H1_DIM, y1lo + (long)t * 128 * H1_DIM,
            R1hi, R1lo, part1, 4 * H1_DIM, H1_DIM, H1_DIM / 8,
            (long)128 * 4 * H1_DIM);
        lstm_gates2<H1_DIM, 8, 2, false><<<BATCH * H1_DIM / 256, 256>>>(
            part1, pre1 + (long)t * 128 * 4 * H1_DIM, (long)2048 * 1024,
            b1, c1,
            y1hi + (long)(t + 1) * 128 * H1_DIM,
            y1lo + (long)(t + 1) * 128 * H1_DIM,
            nullptr);
    }

    // 4) layer-2 input projection (bf16 3-term HMMA): pre2[2048,2048]
    gemm_bf16split<<<dim3(16, 16, 1), 256, GSMEM_TOTAL>>>(
        y1hi + 128 * H1_DIM, y1lo + 128 * H1_DIM,
        W2hi, W2lo, pre2, 2048, H1_DIM, H1_DIM, 0);

    // 5) layer-2 recurrence -> d_out
    for (int t = 0; t < T_STEPS; t++) {
        gemm_bf16split<<<dim3(16, 1, 8), 256, GSMEM_TOTAL>>>(
            h2hi + (long)t * 128 * H2_DIM, h2lo + (long)t * 128 * H2_DIM,
            R2hi, R2lo, part2, 4 * H2_DIM, H2_DIM, H2_DIM / 8,
            (long)128 * 4 * H2_DIM);
        lstm_gates2<H2_DIM, 8, 1, true><<<BATCH * H2_DIM / 256, 256>>>(
            part2, pre2 + (long)t * 128 * 4 * H2_DIM, 0,
            b2, c2,
            h2hi + (long)(t + 1) * 128 * H2_DIM,
            h2lo + (long)(t + 1) * 128 * H2_DIM,
            out + (long)t * 128 * H2_DIM);
    }
}

// round 15
// speedup vs baseline: 1.4380x; 1.4380x over previous
#include <cuda_runtime.h>
#include <cuda_bf16.h>
#include <cuda_fp16.h>
#include <math.h>
#include <stdint.h>

// Problem constants
#define T_STEPS 16
#define BATCH   128
#define IN_DIM  12288
#define H1_DIM  256
#define H2_DIM  512

// ---------------------------------------------------------------------------
// Device-global scratch (no allocation allowed)
// ---------------------------------------------------------------------------
__device__ __align__(256) __half g_Xh  [2048 * 12288];
__device__ __align__(256) __half g_W1h [1024 * 12288];

__device__ __align__(256) __nv_bfloat16 g_W2hi[2048 * 256];
__device__ __align__(256) __nv_bfloat16 g_W2lo[2048 * 256];
__device__ __align__(256) __nv_bfloat16 g_Whh1hi[1024 * 256];
__device__ __align__(256) __nv_bfloat16 g_Whh1lo[1024 * 256];
__device__ __align__(256) __nv_bfloat16 g_Whh2hi[2048 * 512];
__device__ __align__(256) __nv_bfloat16 g_Whh2lo[2048 * 512];

// h sequences incl. leading zero slice: slice s = h after step s-1 (s=0 -> zeros)
__device__ __align__(256) __nv_bfloat16 g_y1hi[17 * 128 * 256];
__device__ __align__(256) __nv_bfloat16 g_y1lo[17 * 128 * 256];
__device__ __align__(256) __nv_bfloat16 g_h2hi[17 * 128 * 512];
__device__ __align__(256) __nv_bfloat16 g_h2lo[17 * 128 * 512];

__device__ float g_pre1 [2 * 2048 * 1024];  // GEMM1 K-split partials (z=2)
__device__ float g_pre2 [2048 * 2048];      // [T*B, 4*H2]
__device__ float g_part1[8 * 128 * 1024];   // rec k-split partials layer 1
__device__ float g_part2[8 * 128 * 2048];   // rec k-split partials layer 2
__device__ float g_c1[128 * 256];
__device__ float g_c2[128 * 512];

// fast sigmoid/tanh via approx MUFU ops (rel err ~1e-6, safe at saturation)
__device__ __forceinline__ float sigmoidf_(float x) {
    float t, r;
    asm("ex2.approx.f32 %0, %1;" : "=f"(t) : "f"(-1.4426950408889634f * x));
    asm("rcp.approx.f32 %0, %1;" : "=f"(r) : "f"(1.0f + t));
    return r;
}
__device__ __forceinline__ float tanhf_(float x) {
    return 2.0f * sigmoidf_(2.0f * x) - 1.0f;
}

// ---------------------------------------------------------------------------
// PTX helpers (compute_103-safe: cp.async + ldmatrix + mma.sync only)
// ---------------------------------------------------------------------------
__device__ __forceinline__ uint32_t smem_u32(const void* p) {
    uint32_t a;
    asm("{ .reg .u64 t; cvta.to.shared.u64 t, %1; cvt.u32.u64 %0, t; }"
        : "=r"(a) : "l"(p));
    return a;
}

template <int N>
__device__ __forceinline__ void cpwait() {
    asm volatile("cp.async.wait_group %0;" :: "n"(N));
}

__device__ __forceinline__ void cp16(uint32_t dst, const void* src) {
    asm volatile("cp.async.cg.shared.global [%0], [%1], 16;"
                 :: "r"(dst), "l"(src));
}

__device__ __forceinline__ void cpcommit() {
    asm volatile("cp.async.commit_group;");
}

__device__ __forceinline__ void ldsm4(uint32_t* r, uint32_t addr) {
    asm volatile("ldmatrix.sync.aligned.m8n8.x4.shared.b16 {%0,%1,%2,%3}, [%4];"
                 : "=r"(r[0]), "=r"(r[1]), "=r"(r[2]), "=r"(r[3]) : "r"(addr));
}

__device__ __forceinline__ void mma_bf16(float* d, const uint32_t* a,
                                         uint32_t b0, uint32_t b1) {
    asm("mma.sync.aligned.m16n8k16.row.col.f32.bf16.bf16.f32 "
        "{%0,%1,%2,%3}, {%4,%5,%6,%7}, {%8,%9}, {%0,%1,%2,%3};"
        : "+f"(d[0]), "+f"(d[1]), "+f"(d[2]), "+f"(d[3])
        : "r"(a[0]), "r"(a[1]), "r"(a[2]), "r"(a[3]), "r"(b0), "r"(b1));
}

__device__ __forceinline__ void mma_f16(float* d, const uint32_t* a,
                                        uint32_t b0, uint32_t b1) {
    asm("mma.sync.aligned.m16n8k16.row.col.f32.f16.f16.f32 "
        "{%0,%1,%2,%3}, {%4,%5,%6,%7}, {%8,%9}, {%0,%1,%2,%3};"
        : "+f"(d[0]), "+f"(d[1]), "+f"(d[2]), "+f"(d[3])
        : "r"(a[0]), "r"(a[1]), "r"(a[2]), "r"(a[3]), "r"(b0), "r"(b1));
}

// ---------------------------------------------------------------------------
// Zero the recurrent states (h slice 0 + c)
// ---------------------------------------------------------------------------
__global__ void zero_states_kernel() {
    int i = blockIdx.x * blockDim.x + threadIdx.x;
    if (i < 128 * 256) {
        g_y1hi[i] = __nv_bfloat16(0.0f);
        g_y1lo[i] = __nv_bfloat16(0.0f);
        g_c1[i] = 0.0f;
    }
    if (i < 128 * 512) {
        g_h2hi[i] = __nv_bfloat16(0.0f);
        g_h2lo[i] = __nv_bfloat16(0.0f);
        g_c2[i] = 0.0f;
    }
}

// ---------------------------------------------------------------------------
// fp32 -> (hi, lo) bf16 split
// ---------------------------------------------------------------------------
__global__ void split_kernel(const float* __restrict__ x,
                             __nv_bfloat16* __restrict__ hi,
                             __nv_bfloat16* __restrict__ lo, int n4) {
    int i = blockIdx.x * blockDim.x + threadIdx.x;
    if (i >= n4) return;
    float4 v = ((const float4*)x)[i];
    __nv_bfloat16 h0 = __float2bfloat16(v.x);
    __nv_bfloat16 h1 = __float2bfloat16(v.y);
    __nv_bfloat16 h2 = __float2bfloat16(v.z);
    __nv_bfloat16 h3 = __float2bfloat16(v.w);
    __nv_bfloat16 l0 = __float2bfloat16(v.x - __bfloat162float(h0));
    __nv_bfloat16 l1 = __float2bfloat16(v.y - __bfloat162float(h1));
    __nv_bfloat16 l2 = __float2bfloat16(v.z - __bfloat162float(h2));
    __nv_bfloat16 l3 = __float2bfloat16(v.w - __bfloat162float(h3));
    ((__nv_bfloat162*)hi)[i * 2 + 0] = __nv_bfloat162(h0, h1);
    ((__nv_bfloat162*)hi)[i * 2 + 1] = __nv_bfloat162(h2, h3);
    ((__nv_bfloat162*)lo)[i * 2 + 0] = __nv_bfloat162(l0, l1);
    ((__nv_bfloat162*)lo)[i * 2 + 1] = __nv_bfloat162(l2, l3);
}

// fp32 -> fp16 quantize
__global__ void quant_f16_kernel(const float* __restrict__ x,
                                 __half* __restrict__ hi, int n4) {
    int i = blockIdx.x * blockDim.x + threadIdx.x;
    if (i >= n4) return;
    float4 v = ((const float4*)x)[i];
    ((__half2*)hi)[i * 2 + 0] = __halves2half2(__float2half(v.x), __float2half(v.y));
    ((__half2*)hi)[i * 2 + 1] = __halves2half2(__float2half(v.z), __float2half(v.w));
}

// ---------------------------------------------------------------------------
// Shared GEMM geometry
// ---------------------------------------------------------------------------
#define GSTAGES 3
#define TILE_B 8192                       // one 128x32 x 16-bit tile
#define GSTAGE_BYTES (4 * TILE_B)         // bf16 3-term: 4 tiles/stage
#define GSMEM_TOTAL (GSTAGES * GSTAGE_BYTES)
#define OSTAGE_BYTES (2 * TILE_B)         // f16 1-term: 2 tiles/stage
#define OSMEM_TOTAL (GSTAGES * OSTAGE_BYTES)

// swizzled offset of (row, chunk) within a tile; chunk = 16B = 8 elems
__device__ __forceinline__ uint32_t swz(int row, int c) {
    return (uint32_t)(row * 64 + 16 * (c ^ ((row >> 1) & 3)));
}

// ---------------------------------------------------------------------------
// Split-bf16 HMMA GEMM (3 terms) with optional K-split partials.
// grid = (N/128, M/128, KZ); Ksub = K/KZ (mult of 32); ldK = row stride.
// ---------------------------------------------------------------------------
__global__ __launch_bounds__(256) void gemm_bf16split(
    const __nv_bfloat16* __restrict__ Ahi, const __nv_bfloat16* __restrict__ Alo,
    const __nv_bfloat16* __restrict__ Bhi, const __nv_bfloat16* __restrict__ Blo,
    float* __restrict__ C, int N, int ldK, int Ksub, long partStride)
{
    extern __shared__ __align__(1024) char gsm[];
    const uint32_t sbase = smem_u32(gsm);
    const int tid = threadIdx.x;
    const int wid = tid >> 5;
    const int lane = tid & 31;
    const int m0 = blockIdx.y * 128;
    const int n0 = blockIdx.x * 128;
    const int koff = blockIdx.z * Ksub;
    const int NK = Ksub >> 5;

    C += (long)blockIdx.z * partStride;

    const int wm = (wid & 1) * 64;
    const int wn = (wid >> 1) * 32;

    auto load_chunk = [&](int ko, int s) {
        const uint32_t stg = sbase + s * GSTAGE_BYTES;
        const int k0 = koff + ko * 32;
#pragma unroll
        for (int it = 0; it < 8; it++) {
            int flat = tid + it * 256;
            int tile = flat >> 9;
            int within = flat & 511;
            int row = within >> 2;
            int c = within & 3;
            const __nv_bfloat16* gp;
            if (tile == 0)      gp = Ahi + (long)(m0 + row) * ldK + k0 + c * 8;
            else if (tile == 1) gp = Alo + (long)(m0 + row) * ldK + k0 + c * 8;
            else if (tile == 2) gp = Bhi + (long)(n0 + row) * ldK + k0 + c * 8;
            else                gp = Blo + (long)(n0 + row) * ldK + k0 + c * 8;
            cp16(stg + tile * TILE_B + swz(row, c), gp);
        }
        cpcommit();
    };

    const int npre = (NK < GSTAGES) ? NK : GSTAGES;
    for (int k = 0; k < npre; k++) load_chunk(k, k);

    float acc[4][4][4];
#pragma unroll
    for (int i = 0; i < 4; i++)
#pragma unroll
        for (int j = 0; j < 4; j++)
#pragma unroll
            for (int q = 0; q < 4; q++) acc[i][j][q] = 0.0f;

    const int a_row_off = ((lane >> 3) & 1) * 8 + (lane & 7);
    const int a_k_off = (lane >> 4);
    const int b_row = wn + lane;

    for (int k = 0; k < NK; k++) {
        const int s = k % GSTAGES;
        const int rem = NK - 1 - k;
        if (rem >= GSTAGES - 1)      cpwait<GSTAGES - 1>();
        else if (rem == 1)           cpwait<1>();
        else                         cpwait<0>();
        __syncthreads();

        const uint32_t stg = sbase + s * GSTAGE_BYTES;
        const uint32_t ah = stg;
        const uint32_t al = stg + TILE_B;
        const uint32_t bh = stg + 2 * TILE_B;
        const uint32_t bl = stg + 3 * TILE_B;

#pragma unroll
        for (int ks = 0; ks < 2; ks++) {
            const int kc = ks * 2;
            uint32_t Ah[4][4], Al[4][4];
            uint32_t Bh0[4], Bh1[4], Bl0[4], Bl1[4];
#pragma unroll
            for (int mt = 0; mt < 4; mt++) {
                const int r = wm + mt * 16 + a_row_off;
                ldsm4(Ah[mt], ah + swz(r, kc + a_k_off));
                ldsm4(Al[mt], al + swz(r, kc + a_k_off));
            }
            ldsm4(Bh0, bh + swz(b_row, kc));
            ldsm4(Bh1, bh + swz(b_row, kc + 1));
            ldsm4(Bl0, bl + swz(b_row, kc));
            ldsm4(Bl1, bl + swz(b_row, kc + 1));
#pragma unroll
            for (int mt = 0; mt < 4; mt++)
#pragma unroll
                for (int nt = 0; nt < 4; nt++)
                    mma_bf16(acc[mt][nt], Ah[mt], Bh0[nt], Bh1[nt]);
#pragma unroll
            for (int mt = 0; mt < 4; mt++)
#pragma unroll
                for (int nt = 0; nt < 4; nt++)
                    mma_bf16(acc[mt][nt], Ah[mt], Bl0[nt], Bl1[nt]);
#pragma unroll
            for (int mt = 0; mt < 4; mt++)
#pragma unroll
                for (int nt = 0; nt < 4; nt++)
                    mma_bf16(acc[mt][nt], Al[mt], Bh0[nt], Bh1[nt]);
        }
        __syncthreads();
        if (k + GSTAGES < NK) load_chunk(k + GSTAGES, s);
    }

#pragma unroll
    for (int mt = 0; mt < 4; mt++) {
#pragma unroll
        for (int nt = 0; nt < 4; nt++) {
            const int row = m0 + wm + mt * 16 + (lane >> 2);
            const int col = n0 + wn + nt * 8 + (lane & 3) * 2;
            float2 v0 = make_float2(acc[mt][nt][0], acc[mt][nt][1]);
            float2 v1 = make_float2(acc[mt][nt][2], acc[mt][nt][3]);
            *(float2*)&C[(long)row * N + col] = v0;
            *(float2*)&C[(long)(row + 8) * N + col] = v1;
        }
    }
}

// ---------------------------------------------------------------------------
// fp16 1-term GEMM (GEMM1): C = A_f16 * B_f16^T, fp32 accum.
// 2 smem tiles per stage. grid = (N/128, M/128, KZ).
// ---------------------------------------------------------------------------
__global__ __launch_bounds__(256) void gemm_f16_1term(
    const __half* __restrict__ A, const __half* __restrict__ B,
    float* __restrict__ C, int N, int ldK, int Ksub, long partStride)
{
    extern __shared__ __align__(1024) char gsm[];
    const uint32_t sbase = smem_u32(gsm);
    const int tid = threadIdx.x;
    const int wid = tid >> 5;
    const int lane = tid & 31;
    const int m0 = blockIdx.y * 128;
    const int n0 = blockIdx.x * 128;
    const int koff = blockIdx.z * Ksub;
    const int NK = Ksub >> 5;

    C += (long)blockIdx.z * partStride;

    const int wm = (wid & 1) * 64;
    const int wn = (wid >> 1) * 32;

    auto load_chunk = [&](int ko, int s) {
        const uint32_t stg = sbase + s * OSTAGE_BYTES;
        const int k0 = koff + ko * 32;
#pragma unroll
        for (int it = 0; it < 4; it++) {
            int flat = tid + it * 256;        // 0..1023
            int tile = flat >> 9;             // 0..1
            int within = flat & 511;
            int row = within >> 2;
            int c = within & 3;
            const __half* gp = (tile == 0)
                ? A + (long)(m0 + row) * ldK + k0 + c * 8
                : B + (long)(n0 + row) * ldK + k0 + c * 8;
            cp16(stg + tile * TILE_B + swz(row, c), gp);
        }
        cpcommit();
    };

    const int npre = (NK < GSTAGES) ? NK : GSTAGES;
    for (int k = 0; k < npre; k++) load_chunk(k, k);

    float acc[4][4][4];
#pragma unroll
    for (int i = 0; i < 4; i++)
#pragma unroll
        for (int j = 0; j < 4; j++)
#pragma unroll
            for (int q = 0; q < 4; q++) acc[i][j][q] = 0.0f;

    const int a_row_off = ((lane >> 3) & 1) * 8 + (lane & 7);
    const int a_k_off = (lane >> 4);
    const int b_row = wn + lane;

    for (int k = 0; k < NK; k++) {
        const int s = k % GSTAGES;
        const int rem = NK - 1 - k;
        if (rem >= GSTAGES - 1)      cpwait<GSTAGES - 1>();
        else if (rem == 1)           cpwait<1>();
        else                         cpwait<0>();
        __syncthreads();

        const uint32_t stg = sbase + s * OSTAGE_BYTES;
        const uint32_t ah = stg;
        const uint32_t bh = stg + TILE_B;

#pragma unroll
        for (int ks = 0; ks < 2; ks++) {
            const int kc = ks * 2;
            uint32_t Ah[4][4];
            uint32_t Bh0[4], Bh1[4];
#pragma unroll
            for (int mt = 0; mt < 4; mt++) {
                const int r = wm + mt * 16 + a_row_off;
                ldsm4(Ah[mt], ah + swz(r, kc + a_k_off));
            }
            ldsm4(Bh0, bh + swz(b_row, kc));
            ldsm4(Bh1, bh + swz(b_row, kc + 1));
#pragma unroll
            for (int mt = 0; mt < 4; mt++)
#pragma unroll
                for (int nt = 0; nt < 4; nt++)
                    mma_f16(acc[mt][nt], Ah[mt], Bh0[nt], Bh1[nt]);
        }
        __syncthreads();
        if (k + GSTAGES < NK) load_chunk(k + GSTAGES, s);
    }

#pragma unroll
    for (int mt = 0; mt < 4; mt++) {
#pragma unroll
        for (int nt = 0; nt < 4; nt++) {
            const int row = m0 + wm + mt * 16 + (lane >> 2);
            const int col = n0 + wn + nt * 8 + (lane & 3) * 2;
            float2 v0 = make_float2(acc[mt][nt][0], acc[mt][nt][1]);
            float2 v1 = make_float2(acc[mt][nt][2], acc[mt][nt][3]);
            *(float2*)&C[(long)row * N + col] = v0;
            *(float2*)&C[(long)(row + 8) * N + col] = v1;
        }
    }
}

// ---------------------------------------------------------------------------
// Gate kernel: sum KZ rec partials + PREZ pre slices + bias, nonlinearity,
// c/h update; h emitted as bf16 hi/lo (next-step GEMM input), optional fp32 y.
// ---------------------------------------------------------------------------
template <int H, int KZ, int PREZ, bool L2OUT>
__global__ __launch_bounds__(256) void lstm_gates2(
    const float* __restrict__ part,     // [KZ][128][4H]
    const float* __restrict__ pre,      // offset to t; slices stride = pstride
    long pstride,
    const float* __restrict__ bias,     // [4H]
    float* __restrict__ c,              // [128][H]
    __nv_bfloat16* __restrict__ hhi,    // next h slice (hi)
    __nv_bfloat16* __restrict__ hlo,    // next h slice (lo)
    float* __restrict__ out)            // fp32 y slice (layer 2) or unused
{
    const int idx = blockIdx.x * 256 + threadIdx.x;   // b*H + j
    const int b = idx / H;
    const int j = idx % H;

    float gate[4];
#pragma unroll
    for (int g = 0; g < 4; g++) {
        const int o = b * 4 * H + g * H + j;
        float v = bias[g * H + j];
#pragma unroll
        for (int z = 0; z < PREZ; z++) v += pre[(long)z * pstride + o];
#pragma unroll
        for (int z = 0; z < KZ; z++) v += part[(long)z * (128 * 4 * H) + o];
        gate[g] = v;
    }

    const float cold = c[idx];
    const float cn = sigmoidf_(gate[1]) * cold + sigmoidf_(gate[0]) * tanhf_(gate[2]);
    const float hn = sigmoidf_(gate[3]) * tanhf_(cn);

    c[idx] = cn;
    __nv_bfloat16 hv = __float2bfloat16(hn);
    hhi[idx] = hv;
    hlo[idx] = __float2bfloat16(hn - __bfloat162float(hv));
    if (L2OUT) out[idx] = hn;
}

// ---------------------------------------------------------------------------
extern "C" void kernel_launch(void* const* d_in, const int* in_sizes, int n_in,
                              void* d_out, int out_size)
{
    const float* inp  = (const float*)d_in[0];   // [128,16,12288] flat [2048,12288]
    const float* Wih1 = (const float*)d_in[1];   // [1024,12288]
    const float* Whh1 = (const float*)d_in[2];   // [1024,256]
    const float* b1   = (const float*)d_in[3];   // [1024]
    const float* Wih2 = (const float*)d_in[4];   // [2048,256]
    const float* Whh2 = (const float*)d_in[5];   // [2048,512]
    const float* b2   = (const float*)d_in[6];   // [2048]
    float* out = (float*)d_out;                  // [16,128,512] flat

    __half *Xh, *W1h;
    __nv_bfloat16 *W2hi, *W2lo;
    __nv_bfloat16 *R1hi, *R1lo, *R2hi, *R2lo, *y1hi, *y1lo, *h2hi, *h2lo;
    float *pre1, *pre2, *part1, *part2, *c1, *c2;
    cudaGetSymbolAddress((void**)&Xh,   g_Xh);
    cudaGetSymbolAddress((void**)&W1h,  g_W1h);
    cudaGetSymbolAddress((void**)&W2hi, g_W2hi);
    cudaGetSymbolAddress((void**)&W2lo, g_W2lo);
    cudaGetSymbolAddress((void**)&R1hi, g_Whh1hi);
    cudaGetSymbolAddress((void**)&R1lo, g_Whh1lo);
    cudaGetSymbolAddress((void**)&R2hi, g_Whh2hi);
    cudaGetSymbolAddress((void**)&R2lo, g_Whh2lo);
    cudaGetSymbolAddress((void**)&y1hi, g_y1hi);
    cudaGetSymbolAddress((void**)&y1lo, g_y1lo);
    cudaGetSymbolAddress((void**)&h2hi, g_h2hi);
    cudaGetSymbolAddress((void**)&h2lo, g_h2lo);
    cudaGetSymbolAddress((void**)&pre1, g_pre1);
    cudaGetSymbolAddress((void**)&pre2, g_pre2);
    cudaGetSymbolAddress((void**)&part1, g_part1);
    cudaGetSymbolAddress((void**)&part2, g_part2);
    cudaGetSymbolAddress((void**)&c1, g_c1);
    cudaGetSymbolAddress((void**)&c2, g_c2);

    cudaFuncSetAttribute(gemm_bf16split,
                         cudaFuncAttributeMaxDynamicSharedMemorySize, GSMEM_TOTAL);
    cudaFuncSetAttribute(gemm_f16_1term,
                         cudaFuncAttributeMaxDynamicSharedMemorySize, OSMEM_TOTAL);

    // 0) fresh recurrent state (h slice 0 = 0, c = 0)
    zero_states_kernel<<<256, 256>>>();

    // 1) precision conversions
    quant_f16_kernel<<<(2048 * 12288 / 4 + 255) / 256, 256>>>(inp, Xh, 2048 * 12288 / 4);
    quant_f16_kernel<<<(1024 * 12288 / 4 + 255) / 256, 256>>>(Wih1, W1h, 1024 * 12288 / 4);
    split_kernel<<<(2048 * 256 / 4 + 255) / 256, 256>>>(Wih2, W2hi, W2lo, 2048 * 256 / 4);
    split_kernel<<<(1024 * 256 / 4 + 255) / 256, 256>>>(Whh1, R1hi, R1lo, 1024 * 256 / 4);
    split_kernel<<<(2048 * 512 / 4 + 255) / 256, 256>>>(Whh2, R2hi, R2lo, 2048 * 512 / 4);

    // 2) layer-1 input projection (fp16 1-term HMMA, K-split x2): pre1[2][2048,1024]
    gemm_f16_1term<<<dim3(8, 16, 2), 256, OSMEM_TOTAL>>>(
        Xh, W1h, pre1, 1024, IN_DIM, IN_DIM / 2, (long)2048 * 1024);

    // 3) layer-1 recurrence: per step, HMMA k-split partial GEMM + gates
    for (int t = 0; t < T_STEPS; t++) {
        gemm_bf16split<<<dim3(8, 1, 8), 256, GSMEM_TOTAL>>>(
            y1hi + (long)t * 128 * H1_DIM, y1lo + (long)t * 128 * H1_DIM,
            R1hi, R1lo, part1, 4 * H1_DIM, H1_DIM, H1_DIM / 8,
            (long)128 * 4 * H1_DIM);
        lstm_gates2<H1_DIM, 8, 2, false><<<BATCH * H1_DIM / 256, 256>>>(
            part1, pre1 + (long)t * 128 * 4 * H1_DIM, (long)2048 * 1024,
            b1, c1,
            y1hi + (long)(t + 1) * 128 * H1_DIM,
            y1lo + (long)(t + 1) * 128 * H1_DIM,
            nullptr);
    }

    // 4) layer-2 input projection (bf16 3-term HMMA): pre2[2048,2048]
    gemm_bf16split<<<dim3(16, 16, 1), 256, GSMEM_TOTAL>>>(
        y1hi + 128 * H1_DIM, y1lo + 128 * H1_DIM,
        W2hi, W2lo, pre2, 2048, H1_DIM, H1_DIM, 0);

    // 5) layer-2 recurrence -> d_out
    for (int t = 0; t < T_STEPS; t++) {
        gemm_bf16split<<<dim3(16, 1, 8), 256, GSMEM_TOTAL>>>(
            h2hi + (long)t * 128 * H2_DIM, h2lo + (long)t * 128 * H2_DIM,
            R2hi, R2lo, part2, 4 * H2_DIM, H2_DIM, H2_DIM / 8,
            (long)128 * 4 * H2_DIM);
        lstm_gates2<H2_DIM, 8, 1, true><<<BATCH * H2_DIM / 256, 256>>>(
            part2, pre2 + (long)t * 128 * 4 * H2_DIM, 0,
            b2, c2,
            h2hi + (long)(t + 1) * 128 * H2_DIM,
            h2lo + (long)(t + 1) * 128 * H2_DIM,
            out + (long)t * 128 * H2_DIM);
    }
}